// round 10
// baseline (speedup 1.0000x reference)
#include <cuda_runtime.h>
#include <cuda_fp16.h>
#include <cstdint>

#define NI 50000
#define NO 5000
#define BATCH 128
#define NNZ_MAX 1000000
#define CAP 1024   // bucket capacity per output col (mean 200, sigma ~14)

// -------- scratch (static __device__ — zero-initialized at module load) --------
__device__ __half2 g_xTh[(size_t)NI * (BATCH / 2)]; // 12.8 MB, fp16 xT[i][b]
__device__ int2    g_edges[(size_t)NO * CAP];       // 41 MB, bucketed (row, w-bits)
__device__ int     g_cnt[NO];                       // zeroed by k_spmm epilogue each call

// decode 32 bits (two fp16) -> float2
__device__ __forceinline__ float2 h2f2(unsigned u) {
    __half2 h = *reinterpret_cast<__half2*>(&u);
    return __half22float2(h);
}

// decode one float4 (8 halves) and FMA into 8 fp32 accumulators
__device__ __forceinline__ void acc8(float* acc, float4 xv, float wv) {
    float2 a0 = h2f2(__float_as_uint(xv.x));
    float2 a1 = h2f2(__float_as_uint(xv.y));
    float2 a2 = h2f2(__float_as_uint(xv.z));
    float2 a3 = h2f2(__float_as_uint(xv.w));
    acc[0] += a0.x * wv; acc[1] += a0.y * wv;
    acc[2] += a1.x * wv; acc[3] += a1.y * wv;
    acc[4] += a2.x * wv; acc[5] += a2.y * wv;
    acc[6] += a3.x * wv; acc[7] += a3.y * wv;
}

// -------- 1: fused prep: scatter blocks [0, s_blocks) + transpose blocks after --------
__global__ void __launch_bounds__(256) k_prep(const float* __restrict__ x,
                                              const void* __restrict__ conn,
                                              const float* __restrict__ w,
                                              int nnz, int s_blocks) {
    if ((int)blockIdx.x < s_blocks) {
        // ---- bucket scatter: one thread per edge; per-warp dtype self-detect ----
        int e = blockIdx.x * 256 + threadIdx.x;
        bool valid = (e < nnz);
        int ce = valid ? e : 0;
        // int64 LE (values < 2^31): odd 32-bit word is zero high-half.
        // int32 (row,col): odd words are cols ~U[0,5000); all-zero prob ~5000^-32.
        int2 rc = ((const int2*)conn)[ce];
        unsigned m = __ballot_sync(0xffffffffu, valid && (rc.y != 0));
        bool is64 = (m == 0);
        if (!valid) return;

        int row, col;
        if (is64) {
            longlong2 c = ((const longlong2*)conn)[e];
            row = (int)c.x; col = (int)c.y;
        } else {
            row = rc.x; col = rc.y;
        }
        if ((unsigned)row < NI && (unsigned)col < NO) {
            int p = atomicAdd(&g_cnt[col], 1);
            if (p < CAP)
                g_edges[(size_t)col * CAP + p] = make_int2(row, __float_as_int(w[e]));
        }
    } else {
        // ---- transpose x (BATCH, NI) -> fp16 xT (NI, BATCH), coarsened ----
        __shared__ float tile[BATCH][33];
        int bid = blockIdx.x - s_blocks;
        int i0 = bid * 32;
        int tx = threadIdx.x & 31, ty = threadIdx.x >> 5;   // (32, 8)
        int i = i0 + tx;

        if (i < NI) {
            #pragma unroll
            for (int j = 0; j < 16; j++) {
                int b = ty + 8 * j;        // covers 0..127
                tile[b][tx] = x[(size_t)b * NI + i];
            }
        }
        __syncthreads();

        #pragma unroll
        for (int jj = 0; jj < 4; jj++) {
            int ii = ty + 8 * jj;          // 0..31 within stripe
            int gi = i0 + ii;
            if (gi < NI) {
                __half2 h0 = __float22half2_rn(
                    make_float2(tile[4 * tx + 0][ii], tile[4 * tx + 1][ii]));
                __half2 h1 = __float22half2_rn(
                    make_float2(tile[4 * tx + 2][ii], tile[4 * tx + 3][ii]));
                float2 v;                  // pack as float2 for a single STG.64
                v.x = *reinterpret_cast<float*>(&h0);
                v.y = *reinterpret_cast<float*>(&h1);
                ((float2*)g_xTh)[(size_t)gi * 32 + tx] = v;
            }
        }
    }
}

// -------- 2: SpMM pull: 1 col/block, 8 warps over edge eighths, half-warp pairing --------
// Lanes 0-15 process even edges of each pair, lanes 16-31 odd edges.
// Each lane covers 8 batch elems (one float4 = 8 halves of the xT row).
__global__ void __launch_bounds__(256) k_spmm(const float* __restrict__ bias,
                                              float* __restrict__ out) {
    __shared__ float4 red[7][16][2];       // 3.5 KB: 8-float partials, segs 1..7

    int seg  = threadIdx.x >> 5;           // 0..7 edge segment
    int lane = threadIdx.x & 31;
    int half = lane >> 4;                  // 0: even edges, 1: odd edges
    int l4   = lane & 15;                  // float4 slot = batch 8*l4..8*l4+7
    int col  = blockIdx.x;                 // grid = NO

    int n = g_cnt[col];
    if (n > CAP) n = CAP;
    int e   = (n * seg) >> 3;
    int end = (n * (seg + 1)) >> 3;

    const int2* __restrict__ ed = &g_edges[(size_t)col * CAP];
    const float4* __restrict__ xT4 = (const float4*)g_xTh;  // 16 float4 per row

    float acc[8] = {0.f, 0.f, 0.f, 0.f, 0.f, 0.f, 0.f, 0.f};

    // head peel: make e even so int4 pair-loads are 16B-aligned
    if (e < end && (e & 1)) {
        int2 q = ed[e];
        if (half == 0)
            acc8(acc, xT4[(size_t)q.x * 16 + l4], __int_as_float(q.y));
        e++;
    }
    // main: 4 pairs = 8 edges per iteration
    for (; e + 7 < end; e += 8) {
        int4 p0 = *(const int4*)(ed + e + 0);
        int4 p1 = *(const int4*)(ed + e + 2);
        int4 p2 = *(const int4*)(ed + e + 4);
        int4 p3 = *(const int4*)(ed + e + 6);
        int r0 = half ? p0.z : p0.x;
        int r1 = half ? p1.z : p1.x;
        int r2 = half ? p2.z : p2.x;
        int r3 = half ? p3.z : p3.x;
        float4 x0 = xT4[(size_t)r0 * 16 + l4];
        float4 x1 = xT4[(size_t)r1 * 16 + l4];
        float4 x2 = xT4[(size_t)r2 * 16 + l4];
        float4 x3 = xT4[(size_t)r3 * 16 + l4];
        acc8(acc, x0, __int_as_float(half ? p0.w : p0.y));
        acc8(acc, x1, __int_as_float(half ? p1.w : p1.y));
        acc8(acc, x2, __int_as_float(half ? p2.w : p2.y));
        acc8(acc, x3, __int_as_float(half ? p3.w : p3.y));
    }
    // pair tail
    for (; e + 1 < end; e += 2) {
        int4 p = *(const int4*)(ed + e);
        int r = half ? p.z : p.x;
        float4 xv = xT4[(size_t)r * 16 + l4];
        acc8(acc, xv, __int_as_float(half ? p.w : p.y));
    }
    // final lone edge
    if (e < end) {
        int2 q = ed[e];
        if (half == 0)
            acc8(acc, xT4[(size_t)q.x * 16 + l4], __int_as_float(q.y));
    }

    // combine odd-edge half into even-edge half: lane L += lane L+16
    #pragma unroll
    for (int k = 0; k < 8; k++)
        acc[k] += __shfl_down_sync(0xffffffffu, acc[k], 16);

    if (seg != 0 && half == 0) {
        red[seg - 1][l4][0] = make_float4(acc[0], acc[1], acc[2], acc[3]);
        red[seg - 1][l4][1] = make_float4(acc[4], acc[5], acc[6], acc[7]);
    }
    __syncthreads();

    if (seg == 0 && half == 0) {
        float bv = __ldg(&bias[col]);
        #pragma unroll
        for (int s = 0; s < 7; s++) {
            float4 a = red[s][l4][0];
            float4 b = red[s][l4][1];
            acc[0] += a.x; acc[1] += a.y; acc[2] += a.z; acc[3] += a.w;
            acc[4] += b.x; acc[5] += b.y; acc[6] += b.z; acc[7] += b.w;
        }
        #pragma unroll
        for (int k = 0; k < 8; k++)
            out[(size_t)(l4 * 8 + k) * NO + col] = acc[k] + bv;
    }

    // restore zero-invariant for next call (single owner block per col;
    // all reads of g_cnt[col] happened before the barrier above)
    if (threadIdx.x == 0) g_cnt[col] = 0;
}

extern "C" void kernel_launch(void* const* d_in, const int* in_sizes, int n_in,
                              void* d_out, int out_size) {
    const float* x    = (const float*)d_in[0];
    const void*  conn = (const void*)d_in[1];
    const float* w    = (const float*)d_in[2];
    const float* bias = (const float*)d_in[3];
    float* out = (float*)d_out;
    int nnz = in_sizes[2];
    if (nnz > NNZ_MAX) nnz = NNZ_MAX;

    int s_blocks = (nnz + 255) / 256;
    int t_blocks = (NI + 31) / 32;

    k_prep<<<s_blocks + t_blocks, 256>>>(x, conn, w, nnz, s_blocks);
    k_spmm<<<NO, 256>>>(bias, out);
}